// round 9
// baseline (speedup 1.0000x reference)
#include <cuda_runtime.h>
#include <math.h>
#include <stdint.h>

#define T_LEN 8192
#define T4 (T_LEN / 4)
#define RADIUS 12                 // truncation rel-err ~9e-5 << 1e-3
#define NTAPS (RADIUS + 1)        // 13 one-sided taps incl. x=0
#define CLUSTER 8
#define THREADS 256
#define OPT 4
#define PER_CTA (THREADS * OPT)   // 1024
#define MVEC (PER_CTA / 4 + 8)    // 264 float4: covers X4[vbase-4 .. vbase+259]
#define INV_SQRT_2PI 0.39894228f
#define NOISE_SIGMA 0.01f

__device__ __forceinline__ uint32_t smem_u32(const void* p) {
    uint32_t a;
    asm("{ .reg .u64 t; cvta.to.shared.u64 t, %1; cvt.u32.u64 %0, t; }"
        : "=r"(a) : "l"(p));
    return a;
}
// three independent warp sums, interleaved shfl chains
__device__ __forceinline__ void warp_sum3(float& a, float& b, float& c) {
    #pragma unroll
    for (int o = 16; o > 0; o >>= 1) {
        a += __shfl_xor_sync(0xffffffffu, a, o);
        b += __shfl_xor_sync(0xffffffffu, b, o);
        c += __shfl_xor_sync(0xffffffffu, c, o);
    }
}

__global__ void __launch_bounds__(THREADS, 1) __cluster_dims__(CLUSTER, 1, 1)
k_fused(const float4* __restrict__ X4,
        const float* __restrict__ weight,
        const float* __restrict__ sigma_min,
        const float* __restrict__ sigma_max,
        const float4* __restrict__ noise4,
        float4* __restrict__ out4) {
    __shared__ float4 sM4[MVEC];               // mask window (X already {0,1})
    __shared__ float sG[NTAPS];
    __shared__ float spmn[8], spmx[8];
    __shared__ __align__(8) float2 slot[CLUSTER];
    __shared__ __align__(8) unsigned long long mbar;   // count = 8

    const int tid = threadIdx.x;
    const int wid = tid >> 5;
    const int lid = tid & 31;
    uint32_t rank;
    asm("mov.u32 %0, %%cluster_ctarank;" : "=r"(rank));
    const int vbase = (int)rank * (PER_CTA / 4);
    const uint32_t mbar_a = smem_u32(&mbar);

    // ---- mbarrier init; early cluster arrive (makes init visible to peers) ----
    if (tid == 0)
        asm volatile("mbarrier.init.shared.b64 [%0], %1;" :: "r"(mbar_a), "r"(CLUSTER) : "memory");
    __syncthreads();
    asm volatile("barrier.cluster.arrive.aligned;" ::: "memory");

    // ---- long-latency loads first ----
    float w0 = weight[lid];
    float w1 = weight[lid + 32];
    float w2 = weight[lid + 64];
    float w3 = weight[lid + 96];
    float smn_v = sigma_min[0];
    float smx_v = sigma_max[0];
    float4 nz4 = noise4[vbase + tid];

    // CTA-wide mask stage: X is exactly {0,1}, no conversion.
    #pragma unroll
    for (int i = tid; i < MVEC; i += THREADS) {
        int v4 = vbase - 4 + i;
        float4 xv = make_float4(0.f, 0.f, 0.f, 0.f);
        if (v4 >= 0 && v4 < T4) xv = X4[v4];
        sM4[i] = xv;
    }

    // ---- sG: warp wid -> taps wid and wid+8 (warps 0..4), 4 sigmas/lane ----
    {
        float e0 = __expf(w0), e1 = __expf(w1), e2 = __expf(w2), e3 = __expf(w3);

        float step = (smx_v - smn_v) * (1.0f / 127.0f);
        float s0 = fabsf(smn_v + (float)lid * step);
        float s1 = fabsf(smn_v + (float)(lid + 32) * step);
        float s2 = fabsf(smn_v + (float)(lid + 64) * step);
        float s3 = fabsf(smn_v + (float)(lid + 96) * step);
        float a0 = e0 * INV_SQRT_2PI / s0, c0 = 0.5f / (s0 * s0);
        float a1 = e1 * INV_SQRT_2PI / s1, c1 = 0.5f / (s1 * s1);
        float a2 = e2 * INV_SQRT_2PI / s2, c2 = 0.5f / (s2 * s2);
        float a3 = e3 * INV_SQRT_2PI / s3, c3 = 0.5f / (s3 * s3);

        float xx0 = (float)wid;       xx0 *= xx0;
        float xx1 = (float)(wid + 8); xx1 *= xx1;
        float v0 = a0 * __expf(-xx0 * c0) + a1 * __expf(-xx0 * c1)
                 + a2 * __expf(-xx0 * c2) + a3 * __expf(-xx0 * c3);
        float v1 = a0 * __expf(-xx1 * c0) + a1 * __expf(-xx1 * c1)
                 + a2 * __expf(-xx1 * c2) + a3 * __expf(-xx1 * c3);
        float denom = e0 + e1 + e2 + e3;

        warp_sum3(v0, v1, denom);
        if (lid == 0) {
            float rden = __fdividef(1.0f, denom);
            sG[wid] = v0 * rden;
            if (wid < NTAPS - 8) sG[wid + 8] = v1 * rden;
        }
    }
    __syncthreads();                           // sM4 + sG ready

    float c[NTAPS];
    #pragma unroll
    for (int x = 0; x < NTAPS; ++x) c[x] = sG[x];

    // ---- conv: 4 outputs/thread from 32-float register window (8x LDS.128) ----
    float wr[32];
    {
        const float4* bp = &sM4[tid];          // wr[m] = X[base+4*tid-16+m]
        #pragma unroll
        for (int k = 0; k < 8; ++k) {
            float4 v = bp[k];
            wr[4 * k + 0] = v.x; wr[4 * k + 1] = v.y;
            wr[4 * k + 2] = v.z; wr[4 * k + 3] = v.w;
        }
    }

    float acc[OPT];
    {
        float nzs[4] = {nz4.x, nz4.y, nz4.z, nz4.w};
        #pragma unroll
        for (int j = 0; j < OPT; ++j) {
            float a0 = fmaf(c[0], wr[15 + j], NOISE_SIGMA * nzs[j]);
            float a1 = 0.0f;
            #pragma unroll
            for (int x = 1; x < NTAPS; x += 2) {
                a0 = fmaf(c[x], wr[15 + j - x] + wr[15 + j + x], a0);
                if (x + 1 < NTAPS)
                    a1 = fmaf(c[x + 1], wr[14 + j - x] + wr[16 + j + x], a1);
            }
            acc[j] = a0 + a1;
        }
    }

    // ---- cluster.wait (satisfied long ago) before any remote DSMEM op ----
    asm volatile("barrier.cluster.wait.aligned;" ::: "memory");

    // ---- min/max: thread -> warp -> block ----
    float mn = fminf(fminf(acc[0], acc[1]), fminf(acc[2], acc[3]));
    float mx = fmaxf(fmaxf(acc[0], acc[1]), fmaxf(acc[2], acc[3]));
    #pragma unroll
    for (int o = 16; o > 0; o >>= 1) {
        mn = fminf(mn, __shfl_xor_sync(0xffffffffu, mn, o));
        mx = fmaxf(mx, __shfl_xor_sync(0xffffffffu, mx, o));
    }
    if (lid == 0) { spmn[wid] = mn; spmx[wid] = mx; }
    __syncthreads();

    if (wid == 0) {
        float bmn = spmn[lid & 7];
        float bmx = spmx[lid & 7];
        #pragma unroll
        for (int o = 4; o > 0; o >>= 1) {
            bmn = fminf(bmn, __shfl_xor_sync(0xffffffffu, bmn, o));
            bmx = fmaxf(bmx, __shfl_xor_sync(0xffffffffu, bmx, o));
        }
        if (lid < CLUSTER) {
            // packed {lo,hi} store into peer lid's slot[rank], then
            // release-arrive on peer lid's mbarrier (orders the store).
            uint32_t a = smem_u32(&slot[rank]);
            uint32_t rs, rb;
            asm volatile("mapa.shared::cluster.u32 %0, %1, %2;"
                         : "=r"(rs) : "r"(a), "r"(lid));
            asm volatile("mapa.shared::cluster.u32 %0, %1, %2;"
                         : "=r"(rb) : "r"(mbar_a), "r"(lid));
            unsigned long long pk =
                ((unsigned long long)__float_as_uint(bmx) << 32) | __float_as_uint(bmn);
            asm volatile("st.shared::cluster.u64 [%0], %1;" :: "r"(rs), "l"(pk) : "memory");
            asm volatile("mbarrier.arrive.release.cluster.shared::cluster.b64 _, [%0];"
                         :: "r"(rb) : "memory");
        }
    }

    // ---- wait for all 8 arrivals (phase 0; smem fresh every launch) ----
    {
        uint32_t done;
        asm volatile(
            "{\n\t.reg .pred p;\n\t"
            "mbarrier.try_wait.parity.acquire.cluster.shared::cta.b64 p, [%1], %2;\n\t"
            "selp.b32 %0, 1, 0, p;\n\t}"
            : "=r"(done) : "r"(mbar_a), "r"(0) : "memory");
        if (!done) {
            asm volatile(
                "{\n\t.reg .pred P1;\n\t"
                "W%=:\n\t"
                "mbarrier.try_wait.parity.acquire.cluster.shared::cta.b64 P1, [%0], %1;\n\t"
                "@P1 bra.uni D%=;\n\t"
                "bra.uni W%=;\n\t"
                "D%=:\n\t}"
                :: "r"(mbar_a), "r"(0) : "memory");
        }
    }

    float L = slot[0].x, H = slot[0].y;
    #pragma unroll
    for (int j = 1; j < CLUSTER; ++j) {
        L = fminf(L, slot[j].x);
        H = fmaxf(H, slot[j].y);
    }
    float inv = __fdividef(1.0f, H - L);
    out4[vbase + tid] = make_float4((acc[0] - L) * inv, (acc[1] - L) * inv,
                                    (acc[2] - L) * inv, (acc[3] - L) * inv);
}

extern "C" void kernel_launch(void* const* d_in, const int* in_sizes, int n_in,
                              void* d_out, int out_size) {
    const float4* X4  = (const float4*)d_in[0];
    const float* wgt  = (const float*)d_in[1];
    const float* smin = (const float*)d_in[2];
    const float* smax = (const float*)d_in[3];
    const float4* nz4 = (const float4*)d_in[4];
    float4* out4 = (float4*)d_out;

    k_fused<<<CLUSTER, THREADS>>>(X4, wgt, smin, smax, nz4, out4);
}

// round 10
// speedup vs baseline: 1.2455x; 1.2455x over previous
#include <cuda_runtime.h>
#include <math.h>
#include <stdint.h>

#define T_LEN 8192
#define T4 (T_LEN / 4)
#define RADIUS 12                 // truncation rel-err ~9e-5 << 1e-3
#define NTAPS (RADIUS + 1)        // 13 one-sided taps incl. x=0
#define CLUSTER 8
#define THREADS 256
#define OPT 4
#define PER_CTA (THREADS * OPT)   // 1024
#define MVEC (PER_CTA / 4 + 8)    // 264 float4: covers X4[vbase-4 .. vbase+259]
#define INV_SQRT_2PI 0.39894228f
#define NOISE_SIGMA 0.01f

__device__ __forceinline__ uint32_t smem_u32(const void* p) {
    uint32_t a;
    asm("{ .reg .u64 t; cvta.to.shared.u64 t, %1; cvt.u32.u64 %0, t; }"
        : "=r"(a) : "l"(p));
    return a;
}
// three independent warp sums, interleaved shfl chains
__device__ __forceinline__ void warp_sum3(float& a, float& b, float& c) {
    #pragma unroll
    for (int o = 16; o > 0; o >>= 1) {
        a += __shfl_xor_sync(0xffffffffu, a, o);
        b += __shfl_xor_sync(0xffffffffu, b, o);
        c += __shfl_xor_sync(0xffffffffu, c, o);
    }
}

__global__ void __launch_bounds__(THREADS, 1) __cluster_dims__(CLUSTER, 1, 1)
k_fused(const float4* __restrict__ X4,
        const float* __restrict__ weight,
        const float* __restrict__ sigma_min,
        const float* __restrict__ sigma_max,
        const float4* __restrict__ noise4,
        float4* __restrict__ out4) {
    __shared__ float4 sM4[MVEC];          // mask window (X is already {0,1})
    __shared__ float sG[NTAPS];
    __shared__ float spmn[8], spmx[8];
    __shared__ __align__(8) float2 slot[CLUSTER];   // {lo,hi} per CTA (DSMEM targets)

    const int tid = threadIdx.x;
    const int wid = tid >> 5;                 // 0..7
    const int lid = tid & 31;
    uint32_t rank;
    asm("mov.u32 %0, %%cluster_ctarank;" : "=r"(rank));
    const int vbase = (int)rank * (PER_CTA / 4);

    // ---- long-latency loads first ----
    float4 nz4 = noise4[vbase + tid];
    #pragma unroll
    for (int i = tid; i < MVEC; i += THREADS) {
        int v4 = vbase - 4 + i;
        float4 xv = make_float4(0.f, 0.f, 0.f, 0.f);
        if (v4 >= 0 && v4 < T4) xv = X4[v4];
        sM4[i] = xv;                          // no conversion: X in {0,1}
    }
    // fold noise scale off the critical path
    nz4.x *= NOISE_SIGMA; nz4.y *= NOISE_SIGMA;
    nz4.z *= NOISE_SIGMA; nz4.w *= NOISE_SIGMA;

    // ---- sG: warp wid -> taps wid and wid+8 (warps 0..4), 4 sigmas/lane ----
    {
        float smn_v = sigma_min[0];
        float smx_v = sigma_max[0];
        float e0 = __expf(weight[lid]);
        float e1 = __expf(weight[lid + 32]);
        float e2 = __expf(weight[lid + 64]);
        float e3 = __expf(weight[lid + 96]);

        float step = (smx_v - smn_v) * (1.0f / 127.0f);
        float s0 = fabsf(smn_v + (float)lid * step);
        float s1 = fabsf(smn_v + (float)(lid + 32) * step);
        float s2 = fabsf(smn_v + (float)(lid + 64) * step);
        float s3 = fabsf(smn_v + (float)(lid + 96) * step);
        float a0 = e0 * INV_SQRT_2PI / s0, c0 = 0.5f / (s0 * s0);
        float a1 = e1 * INV_SQRT_2PI / s1, c1 = 0.5f / (s1 * s1);
        float a2 = e2 * INV_SQRT_2PI / s2, c2 = 0.5f / (s2 * s2);
        float a3 = e3 * INV_SQRT_2PI / s3, c3 = 0.5f / (s3 * s3);

        float xx0 = (float)wid;       xx0 *= xx0;
        float xx1 = (float)(wid + 8); xx1 *= xx1;
        float v0 = a0 * __expf(-xx0 * c0) + a1 * __expf(-xx0 * c1)
                 + a2 * __expf(-xx0 * c2) + a3 * __expf(-xx0 * c3);
        float v1 = a0 * __expf(-xx1 * c0) + a1 * __expf(-xx1 * c1)
                 + a2 * __expf(-xx1 * c2) + a3 * __expf(-xx1 * c3);
        float denom = e0 + e1 + e2 + e3;

        warp_sum3(v0, v1, denom);
        if (lid == 0) {
            float rden = __fdividef(1.0f, denom);
            sG[wid] = v0 * rden;
            if (wid < NTAPS - 8) sG[wid + 8] = v1 * rden;   // wid < 5
        }
    }
    __syncthreads();                          // sM4 + sG ready

    // ---- conv: 4 outputs/thread from 32-float register window (8x LDS.128) ----
    float c[NTAPS];
    #pragma unroll
    for (int x = 0; x < NTAPS; ++x) c[x] = sG[x];

    float wr[32];
    {
        const float4* bp = &sM4[tid];         // wr[m] = X[base+4*tid-16+m]
        #pragma unroll
        for (int k = 0; k < 8; ++k) {
            float4 v = bp[k];
            wr[4 * k + 0] = v.x; wr[4 * k + 1] = v.y;
            wr[4 * k + 2] = v.z; wr[4 * k + 3] = v.w;
        }
    }

    float acc[OPT];
    {
        float nzs[4] = {nz4.x, nz4.y, nz4.z, nz4.w};
        #pragma unroll
        for (int j = 0; j < OPT; ++j) {
            float a0 = fmaf(c[0], wr[15 + j], nzs[j]);
            float a1 = 0.0f;
            #pragma unroll
            for (int x = 1; x < NTAPS; x += 2) {
                a0 = fmaf(c[x], wr[15 + j - x] + wr[15 + j + x], a0);
                if (x + 1 < NTAPS)
                    a1 = fmaf(c[x + 1], wr[14 + j - x] + wr[16 + j + x], a1);
            }
            acc[j] = a0 + a1;
        }
    }

    // ---- min/max: thread -> warp -> block -> cluster ----
    float mn = fminf(fminf(acc[0], acc[1]), fminf(acc[2], acc[3]));
    float mx = fmaxf(fmaxf(acc[0], acc[1]), fmaxf(acc[2], acc[3]));
    #pragma unroll
    for (int o = 16; o > 0; o >>= 1) {
        mn = fminf(mn, __shfl_xor_sync(0xffffffffu, mn, o));
        mx = fmaxf(mx, __shfl_xor_sync(0xffffffffu, mx, o));
    }
    if (lid == 0) { spmn[wid] = mn; spmx[wid] = mx; }
    __syncthreads();

    if (wid == 0) {
        float bmn = spmn[lid & 7];
        float bmx = spmx[lid & 7];
        #pragma unroll
        for (int o = 4; o > 0; o >>= 1) {
            bmn = fminf(bmn, __shfl_xor_sync(0xffffffffu, bmn, o));
            bmx = fmaxf(bmx, __shfl_xor_sync(0xffffffffu, bmx, o));
        }
        if (lid < CLUSTER) {                  // one 64-bit DSMEM store per peer
            uint32_t a = smem_u32(&slot[rank]);
            uint32_t r;
            asm volatile("mapa.shared::cluster.u32 %0, %1, %2;"
                         : "=r"(r) : "r"(a), "r"(lid));
            unsigned long long pk =
                ((unsigned long long)__float_as_uint(bmx) << 32) | __float_as_uint(bmn);
            asm volatile("st.shared::cluster.u64 [%0], %1;" :: "r"(r), "l"(pk) : "memory");
        }
    }

    // ---- cluster barrier: releases DSMEM stores, acquires peer stores ----
    asm volatile("barrier.cluster.arrive.aligned;" ::: "memory");
    asm volatile("barrier.cluster.wait.aligned;" ::: "memory");

    float L = slot[0].x, H = slot[0].y;
    #pragma unroll
    for (int j = 1; j < CLUSTER; ++j) {
        L = fminf(L, slot[j].x);
        H = fmaxf(H, slot[j].y);
    }
    float inv = __fdividef(1.0f, H - L);
    out4[vbase + tid] = make_float4((acc[0] - L) * inv, (acc[1] - L) * inv,
                                    (acc[2] - L) * inv, (acc[3] - L) * inv);
}

extern "C" void kernel_launch(void* const* d_in, const int* in_sizes, int n_in,
                              void* d_out, int out_size) {
    const float4* X4  = (const float4*)d_in[0];
    const float* wgt  = (const float*)d_in[1];
    const float* smin = (const float*)d_in[2];
    const float* smax = (const float*)d_in[3];
    const float4* nz4 = (const float4*)d_in[4];
    float4* out4 = (float4*)d_out;

    k_fused<<<CLUSTER, THREADS>>>(X4, wgt, smin, smax, nz4, out4);
}

// round 12
// speedup vs baseline: 1.3413x; 1.0769x over previous
#include <cuda_runtime.h>
#include <math.h>
#include <stdint.h>

#define T_LEN 8192
#define T4 (T_LEN / 4)
#define RADIUS 12                 // truncation rel-err ~9e-5 << 1e-3
#define NTAPS (RADIUS + 1)        // 13 one-sided taps incl. x=0
#define CLUSTER 8
#define THREADS 256
#define OPT 4
#define PER_CTA (THREADS * OPT)   // 1024
#define MVEC (PER_CTA / 4 + 8)    // 264 float4
#define INV_SQRT_2PI 0.39894228f
#define NOISE_SIGMA 0.01f

__device__ __forceinline__ uint32_t smem_u32(const void* p) {
    uint32_t a;
    asm("{ .reg .u64 t; cvta.to.shared.u64 t, %1; cvt.u32.u64 %0, t; }"
        : "=r"(a) : "l"(p));
    return a;
}

__global__ void __launch_bounds__(THREADS, 1) __cluster_dims__(CLUSTER, 1, 1)
k_fused(const float4* __restrict__ X4,
        const float* __restrict__ weight,
        const float* __restrict__ sigma_min,
        const float* __restrict__ sigma_max,
        const float4* __restrict__ noise4,
        float4* __restrict__ out4) {
    __shared__ float4 sM4[MVEC];          // mask window (X is already {0,1})
    __shared__ float spmn[8], spmx[8];
    __shared__ __align__(8) float2 slot[CLUSTER];   // {lo,hi} per CTA

    const int tid = threadIdx.x;
    const int wid = tid >> 5;             // 0..7
    const int lid = tid & 31;
    uint32_t rank;
    asm("mov.u32 %0, %%cluster_ctarank;" : "=r"(rank));
    const int vbase = (int)rank * (PER_CTA / 4);

    // ---- long-latency loads first ----
    float4 nz4 = noise4[vbase + tid];
    #pragma unroll
    for (int i = tid; i < MVEC; i += THREADS) {
        int v4 = vbase - 4 + i;
        float4 xv = make_float4(0.f, 0.f, 0.f, 0.f);
        if (v4 >= 0 && v4 < T4) xv = X4[v4];
        sM4[i] = xv;
    }
    nz4.x *= NOISE_SIGMA; nz4.y *= NOISE_SIGMA;
    nz4.z *= NOISE_SIGMA; nz4.w *= NOISE_SIGMA;

    // ---- every warp redundantly computes ALL 13 taps (no smem, no extra sync)
    // lane owns sigmas {lid, lid+32, lid+64, lid+96}; Gaussian values by
    // multiplicative recurrence; 14 interleaved butterfly reductions.
    float c[NTAPS];
    {
        float smn_v = sigma_min[0];
        float smx_v = sigma_max[0];
        float e0 = __expf(weight[lid]);
        float e1 = __expf(weight[lid + 32]);
        float e2 = __expf(weight[lid + 64]);
        float e3 = __expf(weight[lid + 96]);
        float denom = e0 + e1 + e2 + e3;

        float step = (smx_v - smn_v) * (1.0f / 127.0f);
        float s0 = fabsf(smn_v + (float)lid * step);
        float s1 = fabsf(smn_v + (float)(lid + 32) * step);
        float s2 = fabsf(smn_v + (float)(lid + 64) * step);
        float s3 = fabsf(smn_v + (float)(lid + 96) * step);

        // g starts at weighted peak; per-step ratio f = exp(-c(2x+1)), f *= exp(-2c)
        float g0 = e0 * INV_SQRT_2PI / s0, cc0 = 0.5f / (s0 * s0);
        float g1 = e1 * INV_SQRT_2PI / s1, cc1 = 0.5f / (s1 * s1);
        float g2 = e2 * INV_SQRT_2PI / s2, cc2 = 0.5f / (s2 * s2);
        float g3 = e3 * INV_SQRT_2PI / s3, cc3 = 0.5f / (s3 * s3);
        float f0 = __expf(-cc0), q0 = f0 * f0;
        float f1 = __expf(-cc1), q1 = f1 * f1;
        float f2 = __expf(-cc2), q2 = f2 * f2;
        float f3 = __expf(-cc3), q3 = f3 * f3;

        #pragma unroll
        for (int x = 0; x < NTAPS; ++x) {
            c[x] = (g0 + g1) + (g2 + g3);
            g0 *= f0; f0 *= q0;
            g1 *= f1; f1 *= q1;
            g2 *= f2; f2 *= q2;
            g3 *= f3; f3 *= q3;
        }

        // 14 interleaved butterflies: all lanes end with full sums
        #pragma unroll
        for (int o = 16; o > 0; o >>= 1) {
            denom += __shfl_xor_sync(0xffffffffu, denom, o);
            #pragma unroll
            for (int x = 0; x < NTAPS; ++x)
                c[x] += __shfl_xor_sync(0xffffffffu, c[x], o);
        }
        float rden = __fdividef(1.0f, denom);
        #pragma unroll
        for (int x = 0; x < NTAPS; ++x) c[x] *= rden;
    }

    __syncthreads();                      // sM4 ready (only block sync)

    // ---- conv: 4 outputs/thread from 32-float register window (8x LDS.128) ----
    float wr[32];
    {
        const float4* bp = &sM4[tid];     // wr[m] = X[base+4*tid-16+m]
        #pragma unroll
        for (int k = 0; k < 8; ++k) {
            float4 v = bp[k];
            wr[4 * k + 0] = v.x; wr[4 * k + 1] = v.y;
            wr[4 * k + 2] = v.z; wr[4 * k + 3] = v.w;
        }
    }

    float acc[OPT];
    {
        float nzs[4] = {nz4.x, nz4.y, nz4.z, nz4.w};
        #pragma unroll
        for (int j = 0; j < OPT; ++j) {
            float a0 = fmaf(c[0], wr[15 + j], nzs[j]);
            float a1 = 0.0f;
            #pragma unroll
            for (int x = 1; x < NTAPS; x += 2) {
                a0 = fmaf(c[x], wr[15 + j - x] + wr[15 + j + x], a0);
                if (x + 1 < NTAPS)
                    a1 = fmaf(c[x + 1], wr[14 + j - x] + wr[16 + j + x], a1);
            }
            acc[j] = a0 + a1;
        }
    }

    // ---- min/max: thread -> warp -> block -> cluster ----
    float mn = fminf(fminf(acc[0], acc[1]), fminf(acc[2], acc[3]));
    float mx = fmaxf(fmaxf(acc[0], acc[1]), fmaxf(acc[2], acc[3]));
    #pragma unroll
    for (int o = 16; o > 0; o >>= 1) {
        mn = fminf(mn, __shfl_xor_sync(0xffffffffu, mn, o));
        mx = fmaxf(mx, __shfl_xor_sync(0xffffffffu, mx, o));
    }
    if (lid == 0) { spmn[wid] = mn; spmx[wid] = mx; }
    __syncthreads();

    if (wid == 0) {
        float bmn = spmn[lid & 7];
        float bmx = spmx[lid & 7];
        #pragma unroll
        for (int o = 4; o > 0; o >>= 1) {
            bmn = fminf(bmn, __shfl_xor_sync(0xffffffffu, bmn, o));
            bmx = fmaxf(bmx, __shfl_xor_sync(0xffffffffu, bmx, o));
        }
        if (lid < CLUSTER) {              // one 64-bit DSMEM store per peer
            uint32_t a = smem_u32(&slot[rank]);
            uint32_t r;
            asm volatile("mapa.shared::cluster.u32 %0, %1, %2;"
                         : "=r"(r) : "r"(a), "r"(lid));
            unsigned long long pk =
                ((unsigned long long)__float_as_uint(bmx) << 32) | __float_as_uint(bmn);
            asm volatile("st.shared::cluster.u64 [%0], %1;" :: "r"(r), "l"(pk) : "memory");
        }
    }

    // ---- cluster barrier: releases DSMEM stores, acquires peer stores ----
    asm volatile("barrier.cluster.arrive.aligned;" ::: "memory");
    asm volatile("barrier.cluster.wait.aligned;" ::: "memory");

    float L = slot[0].x, H = slot[0].y;
    #pragma unroll
    for (int j = 1; j < CLUSTER; ++j) {
        L = fminf(L, slot[j].x);
        H = fmaxf(H, slot[j].y);
    }
    float inv = __fdividef(1.0f, H - L);
    out4[vbase + tid] = make_float4((acc[0] - L) * inv, (acc[1] - L) * inv,
                                    (acc[2] - L) * inv, (acc[3] - L) * inv);
}

extern "C" void kernel_launch(void* const* d_in, const int* in_sizes, int n_in,
                              void* d_out, int out_size) {
    const float4* X4  = (const float4*)d_in[0];
    const float* wgt  = (const float*)d_in[1];
    const float* smin = (const float*)d_in[2];
    const float* smax = (const float*)d_in[3];
    const float4* nz4 = (const float4*)d_in[4];
    float4* out4 = (float4*)d_out;

    k_fused<<<CLUSTER, THREADS>>>(X4, wgt, smin, smax, nz4, out4);
}